// round 14
// baseline (speedup 1.0000x reference)
#include <cuda_runtime.h>
#include <math.h>

#define N 1024
#define C 128
#define H 4
#define HD 32
#define HID 64
#define TI 32
#define TJ 64
#define NJB (N / TJ)

typedef unsigned long long u64;

// ---- packed f32x2 helpers (sm_103a) ----
#define PACK2(d, lo, hi) asm("mov.b64 %0, {%1, %2};" : "=l"(d) : "f"(lo), "f"(hi))
#define UNPACK2(lo, hi, s) asm("mov.b64 {%0, %1}, %2;" : "=f"(lo), "=f"(hi) : "l"(s))
#define ADD2(d, a, b) asm("add.rn.f32x2 %0, %1, %2;" : "=l"(d) : "l"(a), "l"(b))
#define FMA2(d, a, b) asm("fma.rn.f32x2 %0, %1, %2, %0;" : "+l"(d) : "l"(a), "l"(b))

// ---- scratch (device globals) ----
__device__ float  g_q[N * C];
__device__ float  g_k[N * C];
__device__ float  g_v[N * C];
__device__ float4 g_A4[N * HID];
__device__ float  g_qb2[N * H];
__device__ float  g_Pib[N * HID];
__device__ float  g_negPj[N * HID];
__device__ float  g_es[(size_t)H * N * N];     // exp(score), L2-resident
__device__ float  g_psum[N * H * NJB];         // row-sum partials [i][h][jb]

// ---------------------------------------------------------------
// K1: qkv GEMM. grid (N/8, 3), block 256.
// ---------------------------------------------------------------
__global__ void __launch_bounds__(256) qkv_kernel(
        const float* __restrict__ x, const float* __restrict__ y,
        const float* __restrict__ Wq, const float* __restrict__ bq,
        const float* __restrict__ Wk, const float* __restrict__ bk,
        const float* __restrict__ Wv, const float* __restrict__ bv) {
    int n0 = blockIdx.x * 8;
    int which = blockIdx.y;
    const float* in = (which == 0) ? x : y;
    const float* W  = (which == 0) ? Wq : (which == 1 ? Wk : Wv);
    const float* b  = (which == 0) ? bq : (which == 1 ? bk : bv);
    float* out      = (which == 0) ? g_q : (which == 1 ? g_k : g_v);

    __shared__ __align__(16) float xsT[C][12];

    int t = threadIdx.x;
    for (int idx = t; idx < 8 * C; idx += 256) {
        int r = idx >> 7, c = idx & 127;
        xsT[c][r] = in[(n0 + r) * C + c];
    }
    __syncthreads();

    int c  = t & 127;
    int rh = (t >> 7) * 4;
    float bc = b[c];
    float a0 = bc, a1 = bc, a2 = bc, a3 = bc;

#pragma unroll 8
    for (int k = 0; k < C; k++) {
        float w = W[k * C + c];
        float4 xv = *(const float4*)&xsT[k][rh];
        a0 += xv.x * w;
        a1 += xv.y * w;
        a2 += xv.z * w;
        a3 += xv.w * w;
    }
    out[(n0 + rh + 0) * C + c] = a0;
    out[(n0 + rh + 1) * C + c] = a1;
    out[(n0 + rh + 2) * C + c] = a2;
    out[(n0 + rh + 3) * C + c] = a3;
}

// ---------------------------------------------------------------
// K2: coalesced prep. grid N/16, block 256.
// ---------------------------------------------------------------
__global__ void __launch_bounds__(256) prep_kernel(
        const float* __restrict__ pos,
        const float* __restrict__ W1, const float* __restrict__ b1,
        const float* __restrict__ W2, const float* __restrict__ b2) {
    int i0 = blockIdx.x * 16;
    __shared__ float W2s[HID][C + 1];
    __shared__ float qs[16][C];
    __shared__ float b2s[C];

    int t = threadIdx.x;
    for (int idx = t; idx < HID * C; idx += 256)
        W2s[idx >> 7][idx & 127] = W2[idx];
    for (int idx = t; idx < 16 * C; idx += 256)
        qs[idx >> 7][idx & 127] = g_q[(i0 + (idx >> 7)) * C + (idx & 127)];
    if (t < C) b2s[t] = b2[t];
    __syncthreads();

    int m = t & 63;
    int isub = t >> 6;
    float w1x = W1[m], w1y = W1[HID + m], w1z = W1[2 * HID + m];
    float b1m = b1[m];

#pragma unroll
    for (int p = 0; p < 4; p++) {
        int il = p * 4 + isub;
        int i = i0 + il;
        const float* qrow = qs[il];

        float4 a = make_float4(0.f, 0.f, 0.f, 0.f);
#pragma unroll
        for (int d = 0; d < HD; d++) {
            a.x += W2s[m][0 * HD + d] * qrow[0 * HD + d];
            a.y += W2s[m][1 * HD + d] * qrow[1 * HD + d];
            a.z += W2s[m][2 * HD + d] * qrow[2 * HD + d];
            a.w += W2s[m][3 * HD + d] * qrow[3 * HD + d];
        }
        g_A4[i * HID + m] = a;

        float px = pos[i * 3 + 0], py = pos[i * 3 + 1], pz = pos[i * 3 + 2];
        float p1 = px * w1x + py * w1y + pz * w1z;
        g_negPj[i * HID + m] = -p1;
        g_Pib[i * HID + m]   = p1 + b1m;

        if (m < H) {
            float s = 0.f;
#pragma unroll
            for (int d = 0; d < HD; d++) s += qrow[m * HD + d] * b2s[m * HD + d];
            g_qb2[i * H + m] = s;
        }
    }
}

// ---------------------------------------------------------------
// K3: scores -> es = exp(score) + row-sum partials via shuffle.
// ---------------------------------------------------------------
struct ScoresSmem {
    float  qs[TI][132];
    float  ksT[C][TJ + 4];
    float  Pib[TI][HID];
    float  nPjT[HID][TJ + 4];
    float4 A4[TI][HID + 2];
    float  pis[TI][3];
    float  pjs[TJ][3];
    float  qb2[TI][4];
};

__global__ void __launch_bounds__(256, 2) scores_kernel(const float* __restrict__ pos) {
    extern __shared__ __align__(16) char s_raw[];
    ScoresSmem& s = *reinterpret_cast<ScoresSmem*>(s_raw);

    int jb = blockIdx.x;
    int i0 = blockIdx.y * TI;
    int j0 = jb * TJ;
    int tid = threadIdx.x;
    const float inv_sqrt_hd = 0.17677669529663687f;

    {
        const float4* gq4 = (const float4*)g_q;
        for (int t = tid; t < TI * 32; t += 256) {
            int r = t >> 5, c4 = t & 31;
            float4 v = gq4[(i0 + r) * 32 + c4];
            v.x *= inv_sqrt_hd; v.y *= inv_sqrt_hd; v.z *= inv_sqrt_hd; v.w *= inv_sqrt_hd;
            *(float4*)&s.qs[r][c4 * 4] = v;
        }
        const float4* gk4 = (const float4*)g_k;
        for (int t = tid; t < TJ * 32; t += 256) {
            int j = t >> 5, c4 = t & 31;
            float4 v = gk4[(j0 + j) * 32 + c4];
            s.ksT[c4 * 4 + 0][j] = v.x;
            s.ksT[c4 * 4 + 1][j] = v.y;
            s.ksT[c4 * 4 + 2][j] = v.z;
            s.ksT[c4 * 4 + 3][j] = v.w;
        }
        const float4* gp4 = (const float4*)g_negPj;
        for (int t = tid; t < TJ * 16; t += 256) {
            int j = t >> 4, m4 = t & 15;
            float4 v = gp4[(j0 + j) * 16 + m4];
            s.nPjT[m4 * 4 + 0][j] = v.x;
            s.nPjT[m4 * 4 + 1][j] = v.y;
            s.nPjT[m4 * 4 + 2][j] = v.z;
            s.nPjT[m4 * 4 + 3][j] = v.w;
        }
    }
    for (int t = tid; t < TI * HID; t += 256) {
        int r = t >> 6, m = t & 63;
        s.Pib[r][m] = g_Pib[(i0 + r) * HID + m];
        s.A4[r][m]  = g_A4[(i0 + r) * HID + m];
    }
    if (tid < TI) {
        s.pis[tid][0] = pos[(i0 + tid) * 3 + 0];
        s.pis[tid][1] = pos[(i0 + tid) * 3 + 1];
        s.pis[tid][2] = pos[(i0 + tid) * 3 + 2];
    }
    if (tid < TJ) {
        s.pjs[tid][0] = pos[(j0 + tid) * 3 + 0];
        s.pjs[tid][1] = pos[(j0 + tid) * 3 + 1];
        s.pjs[tid][2] = pos[(j0 + tid) * 3 + 2];
    }
    if (tid < TI * H) {
        s.qb2[tid >> 2][tid & 3] = g_qb2[(i0 + (tid >> 2)) * H + (tid & 3)];
    }
    __syncthreads();

    int il = tid >> 4;
    int jt = tid & 15;
    int ia = il, ib = il + 16;
    int jq = 4 * jt;

    u64 acc[2][4][2];
#pragma unroll
    for (int h = 0; h < 4; h++) {
        float qa = s.qb2[ia][h], qb = s.qb2[ib][h];
        u64 ta, tb;
        PACK2(ta, qa, qa); PACK2(tb, qb, qb);
        acc[0][h][0] = ta; acc[0][h][1] = ta;
        acc[1][h][0] = tb; acc[1][h][1] = tb;
    }

#pragma unroll 4
    for (int m = 0; m < HID; m++) {
        float pa = s.Pib[ia][m], pb = s.Pib[ib][m];
        u64 pa2, pb2;
        PACK2(pa2, pa, pa); PACK2(pb2, pb, pb);
        ulonglong2 nn = *(const ulonglong2*)&s.nPjT[m][jq];

        u64 za0, za1, zb0, zb1;
        ADD2(za0, pa2, nn.x); ADD2(za1, pa2, nn.y);
        ADD2(zb0, pb2, nn.x); ADD2(zb1, pb2, nn.y);

        float lo, hi;
        u64 ha0, ha1, hb0, hb1;
        UNPACK2(lo, hi, za0); PACK2(ha0, fmaxf(lo, 0.f), fmaxf(hi, 0.f));
        UNPACK2(lo, hi, za1); PACK2(ha1, fmaxf(lo, 0.f), fmaxf(hi, 0.f));
        UNPACK2(lo, hi, zb0); PACK2(hb0, fmaxf(lo, 0.f), fmaxf(hi, 0.f));
        UNPACK2(lo, hi, zb1); PACK2(hb1, fmaxf(lo, 0.f), fmaxf(hi, 0.f));

        float4 aa = s.A4[ia][m], ab = s.A4[ib][m];
        u64 ax, ay, az, aw, bx, by, bz, bw;
        PACK2(ax, aa.x, aa.x); PACK2(ay, aa.y, aa.y);
        PACK2(az, aa.z, aa.z); PACK2(aw, aa.w, aa.w);
        PACK2(bx, ab.x, ab.x); PACK2(by, ab.y, ab.y);
        PACK2(bz, ab.z, ab.z); PACK2(bw, ab.w, ab.w);

        FMA2(acc[0][0][0], ha0, ax); FMA2(acc[0][0][1], ha1, ax);
        FMA2(acc[0][1][0], ha0, ay); FMA2(acc[0][1][1], ha1, ay);
        FMA2(acc[0][2][0], ha0, az); FMA2(acc[0][2][1], ha1, az);
        FMA2(acc[0][3][0], ha0, aw); FMA2(acc[0][3][1], ha1, aw);
        FMA2(acc[1][0][0], hb0, bx); FMA2(acc[1][0][1], hb1, bx);
        FMA2(acc[1][1][0], hb0, by); FMA2(acc[1][1][1], hb1, by);
        FMA2(acc[1][2][0], hb0, bz); FMA2(acc[1][2][1], hb1, bz);
        FMA2(acc[1][3][0], hb0, bw); FMA2(acc[1][3][1], hb1, bw);
    }

#pragma unroll
    for (int h = 0; h < 4; h++) {
#pragma unroll
        for (int d2 = 0; d2 < 16; d2++) {
            int c = h * HD + 2 * d2;
            float2 qa = *(const float2*)&s.qs[ia][c];
            float2 qb = *(const float2*)&s.qs[ib][c];
            ulonglong2 k0 = *(const ulonglong2*)&s.ksT[c][jq];
            ulonglong2 k1 = *(const ulonglong2*)&s.ksT[c + 1][jq];
            u64 qa0, qa1, qb0, qb1;
            PACK2(qa0, qa.x, qa.x); PACK2(qa1, qa.y, qa.y);
            PACK2(qb0, qb.x, qb.x); PACK2(qb1, qb.y, qb.y);
            FMA2(acc[0][h][0], qa0, k0.x); FMA2(acc[0][h][1], qa0, k0.y);
            FMA2(acc[0][h][0], qa1, k1.x); FMA2(acc[0][h][1], qa1, k1.y);
            FMA2(acc[1][h][0], qb0, k0.x); FMA2(acc[1][h][1], qb0, k0.y);
            FMA2(acc[1][h][0], qb1, k1.x); FMA2(acc[1][h][1], qb1, k1.y);
        }
    }

    float pax = s.pis[ia][0], pay = s.pis[ia][1], paz = s.pis[ia][2];
    float pbx = s.pis[ib][0], pby = s.pis[ib][1], pbz = s.pis[ib][2];
    float da[4], db[4];
#pragma unroll
    for (int e = 0; e < 4; e++) {
        int j = jq + e;
        float jx = s.pjs[j][0], jy = s.pjs[j][1], jz = s.pjs[j][2];
        float x0 = pax - jx, y0_ = pay - jy, z0 = paz - jz;
        float x1 = pbx - jx, y1_ = pby - jy, z1 = pbz - jz;
        da[e] = sqrtf(x0 * x0 + y0_ * y0_ + z0 * z0);
        db[e] = sqrtf(x1 * x1 + y1_ * y1_ + z1 * z1);
    }

    // --- exp, store, and per-row local sums ---
    int iga = i0 + ia, igb = i0 + ib;
    float lsum[2][4];
#pragma unroll
    for (int h = 0; h < 4; h++) {
        size_t basea = ((size_t)h * N + iga) * N + j0 + jq;
        size_t baseb = ((size_t)h * N + igb) * N + j0 + jq;
        float l0, h0, l1, h1;
        UNPACK2(l0, h0, acc[0][h][0]);
        UNPACK2(l1, h1, acc[0][h][1]);
        float4 ea = make_float4(__expf(l0 - da[0]), __expf(h0 - da[1]),
                                __expf(l1 - da[2]), __expf(h1 - da[3]));
        UNPACK2(l0, h0, acc[1][h][0]);
        UNPACK2(l1, h1, acc[1][h][1]);
        float4 eb = make_float4(__expf(l0 - db[0]), __expf(h0 - db[1]),
                                __expf(l1 - db[2]), __expf(h1 - db[3]));
        *(float4*)&g_es[basea] = ea;
        *(float4*)&g_es[baseb] = eb;
        lsum[0][h] = (ea.x + ea.y) + (ea.z + ea.w);
        lsum[1][h] = (eb.x + eb.y) + (eb.z + eb.w);
    }

    // --- butterfly over the 16 jt-lanes (offsets 1,2,4,8 stay
    //     within the same il half-warp) ---
#pragma unroll
    for (int o = 1; o < 16; o <<= 1) {
#pragma unroll
        for (int h = 0; h < 4; h++) {
            lsum[0][h] += __shfl_xor_sync(0xFFFFFFFFu, lsum[0][h], o);
            lsum[1][h] += __shfl_xor_sync(0xFFFFFFFFu, lsum[1][h], o);
        }
    }
    if (jt == 0) {
#pragma unroll
        for (int h = 0; h < 4; h++) {
            g_psum[(iga * H + h) * NJB + jb] = lsum[0][h];
            g_psum[(igb * H + h) * NJB + jb] = lsum[1][h];
        }
    }
}

// ---------------------------------------------------------------
// K4 v7: scalar PV (no packing, no rsum). grid (N/8, H), block 256.
// Warp owns a 128-j slice, all 8 rows; float4 es used directly.
// ---------------------------------------------------------------
struct PVSmem {
    float red[8][8][33];
};

__global__ void __launch_bounds__(256) pv_kernel(float* __restrict__ out) {
    __shared__ PVSmem s;

    int h = blockIdx.y;
    int i0 = blockIdx.x * 8;
    int warp = threadIdx.x >> 5, lane = threadIdx.x & 31;

    float acc[8];
#pragma unroll
    for (int r = 0; r < 8; r++) acc[r] = 0.f;

    const float*  vb = g_v + h * HD + lane;    // column d = lane
    const float4* eb = (const float4*)(g_es + ((size_t)h * N + i0) * N);
    int j4base = warp * 32;

#pragma unroll 2
    for (int j4 = j4base; j4 < j4base + 32; j4++) {
        int j = j4 * 4;
        float v0 = vb[(j + 0) * C];
        float v1 = vb[(j + 1) * C];
        float v2 = vb[(j + 2) * C];
        float v3 = vb[(j + 3) * C];
#pragma unroll
        for (int r = 0; r < 8; r++) {
            float4 e = eb[(size_t)r * (N / 4) + j4];
            acc[r] += e.x * v0 + e.y * v1 + e.z * v2 + e.w * v3;
        }
    }

#pragma unroll
    for (int r = 0; r < 8; r++) s.red[warp][r][lane] = acc[r];
    __syncthreads();

    // 256 outputs (8 rows x 32 d), one per thread; sums from g_psum
    {
        int o = threadIdx.x;
        int r = o >> 5, d = o & 31;
        float v = 0.f;
#pragma unroll
        for (int w = 0; w < 8; w++) v += s.red[w][r][d];

        const float4* ps = (const float4*)&g_psum[((i0 + r) * H + h) * NJB];
        float4 p0 = ps[0], p1 = ps[1], p2 = ps[2], p3 = ps[3];
        float sm = ((p0.x + p0.y) + (p0.z + p0.w)) + ((p1.x + p1.y) + (p1.z + p1.w))
                 + ((p2.x + p2.y) + (p2.z + p2.w)) + ((p3.x + p3.y) + (p3.z + p3.w));
        out[(i0 + r) * C + h * HD + d] = v / sm;
    }
}

// ---------------------------------------------------------------
extern "C" void kernel_launch(void* const* d_in, const int* in_sizes, int n_in,
                              void* d_out, int out_size) {
    (void)in_sizes; (void)n_in; (void)out_size;
    const float* x   = (const float*)d_in[0];
    const float* y   = (const float*)d_in[1];
    const float* pos = (const float*)d_in[2];
    const float* Wq  = (const float*)d_in[3];
    const float* bq  = (const float*)d_in[4];
    const float* Wk  = (const float*)d_in[5];
    const float* bk  = (const float*)d_in[6];
    const float* Wv  = (const float*)d_in[7];
    const float* bv  = (const float*)d_in[8];
    const float* W1  = (const float*)d_in[9];
    const float* b1  = (const float*)d_in[10];
    const float* W2  = (const float*)d_in[11];
    const float* b2  = (const float*)d_in[12];
    float* out = (float*)d_out;

    static bool attrs_set = false;
    if (!attrs_set) {
        cudaFuncSetAttribute(scores_kernel, cudaFuncAttributeMaxDynamicSharedMemorySize,
                             (int)sizeof(ScoresSmem));
        attrs_set = true;
    }

    qkv_kernel<<<dim3(N / 8, 3), 256>>>(x, y, Wq, bq, Wk, bk, Wv, bv);
    prep_kernel<<<N / 16, 256>>>(pos, W1, b1, W2, b2);
    scores_kernel<<<dim3(NJB, N / TI), 256, sizeof(ScoresSmem)>>>(pos);
    pv_kernel<<<dim3(N / 8, H), 256>>>(out);
}

// round 16
// speedup vs baseline: 1.0815x; 1.0815x over previous
#include <cuda_runtime.h>
#include <math.h>
#include <stdint.h>

#define N 1024
#define C 128
#define H 4
#define HD 32
#define HID 64
#define TI 32
#define TJ 64
#define NJB (N / TJ)

typedef unsigned long long u64;

// ---- packed f32x2 helpers (sm_103a) ----
#define PACK2(d, lo, hi) asm("mov.b64 %0, {%1, %2};" : "=l"(d) : "f"(lo), "f"(hi))
#define UNPACK2(lo, hi, s) asm("mov.b64 {%0, %1}, %2;" : "=f"(lo), "=f"(hi) : "l"(s))
#define ADD2(d, a, b) asm("add.rn.f32x2 %0, %1, %2;" : "=l"(d) : "l"(a), "l"(b))
#define FMA2(d, a, b) asm("fma.rn.f32x2 %0, %1, %2, %0;" : "+l"(d) : "l"(a), "l"(b))

// ---- cp.async helpers ----
#define CP_ASYNC_16(dst, src) \
    asm volatile("cp.async.cg.shared.global [%0], [%1], 16;" :: "r"(dst), "l"(src) : "memory")
#define CP_ASYNC_COMMIT() asm volatile("cp.async.commit_group;" ::: "memory")
#define CP_ASYNC_WAIT1() asm volatile("cp.async.wait_group 1;" ::: "memory")
#define CP_ASYNC_WAIT0() asm volatile("cp.async.wait_group 0;" ::: "memory")

// ---- scratch (device globals) ----
__device__ float  g_q[N * C];
__device__ float  g_k[N * C];
__device__ float  g_v[N * C];
__device__ float4 g_A4[N * HID];
__device__ float  g_qb2[N * H];
__device__ float  g_Pib[N * HID];
__device__ float  g_negPj[N * HID];
__device__ float  g_es[(size_t)H * N * N];     // exp(score), L2-resident
__device__ float  g_psum[N * H * NJB];         // row-sum partials [i][h][jb]

// ---------------------------------------------------------------
// K1: qkv GEMM. grid (N/8, 3), block 256.
// ---------------------------------------------------------------
__global__ void __launch_bounds__(256) qkv_kernel(
        const float* __restrict__ x, const float* __restrict__ y,
        const float* __restrict__ Wq, const float* __restrict__ bq,
        const float* __restrict__ Wk, const float* __restrict__ bk,
        const float* __restrict__ Wv, const float* __restrict__ bv) {
    int n0 = blockIdx.x * 8;
    int which = blockIdx.y;
    const float* in = (which == 0) ? x : y;
    const float* W  = (which == 0) ? Wq : (which == 1 ? Wk : Wv);
    const float* b  = (which == 0) ? bq : (which == 1 ? bk : bv);
    float* out      = (which == 0) ? g_q : (which == 1 ? g_k : g_v);

    __shared__ __align__(16) float xsT[C][12];

    int t = threadIdx.x;
    for (int idx = t; idx < 8 * C; idx += 256) {
        int r = idx >> 7, c = idx & 127;
        xsT[c][r] = in[(n0 + r) * C + c];
    }
    __syncthreads();

    int c  = t & 127;
    int rh = (t >> 7) * 4;
    float bc = b[c];
    float a0 = bc, a1 = bc, a2 = bc, a3 = bc;

#pragma unroll 8
    for (int k = 0; k < C; k++) {
        float w = W[k * C + c];
        float4 xv = *(const float4*)&xsT[k][rh];
        a0 += xv.x * w;
        a1 += xv.y * w;
        a2 += xv.z * w;
        a3 += xv.w * w;
    }
    out[(n0 + rh + 0) * C + c] = a0;
    out[(n0 + rh + 1) * C + c] = a1;
    out[(n0 + rh + 2) * C + c] = a2;
    out[(n0 + rh + 3) * C + c] = a3;
}

// ---------------------------------------------------------------
// K2: coalesced prep. grid N/16, block 256.
// ---------------------------------------------------------------
__global__ void __launch_bounds__(256) prep_kernel(
        const float* __restrict__ pos,
        const float* __restrict__ W1, const float* __restrict__ b1,
        const float* __restrict__ W2, const float* __restrict__ b2) {
    int i0 = blockIdx.x * 16;
    __shared__ float W2s[HID][C + 1];
    __shared__ float qs[16][C];
    __shared__ float b2s[C];

    int t = threadIdx.x;
    for (int idx = t; idx < HID * C; idx += 256)
        W2s[idx >> 7][idx & 127] = W2[idx];
    for (int idx = t; idx < 16 * C; idx += 256)
        qs[idx >> 7][idx & 127] = g_q[(i0 + (idx >> 7)) * C + (idx & 127)];
    if (t < C) b2s[t] = b2[t];
    __syncthreads();

    int m = t & 63;
    int isub = t >> 6;
    float w1x = W1[m], w1y = W1[HID + m], w1z = W1[2 * HID + m];
    float b1m = b1[m];

#pragma unroll
    for (int p = 0; p < 4; p++) {
        int il = p * 4 + isub;
        int i = i0 + il;
        const float* qrow = qs[il];

        float4 a = make_float4(0.f, 0.f, 0.f, 0.f);
#pragma unroll
        for (int d = 0; d < HD; d++) {
            a.x += W2s[m][0 * HD + d] * qrow[0 * HD + d];
            a.y += W2s[m][1 * HD + d] * qrow[1 * HD + d];
            a.z += W2s[m][2 * HD + d] * qrow[2 * HD + d];
            a.w += W2s[m][3 * HD + d] * qrow[3 * HD + d];
        }
        g_A4[i * HID + m] = a;

        float px = pos[i * 3 + 0], py = pos[i * 3 + 1], pz = pos[i * 3 + 2];
        float p1 = px * w1x + py * w1y + pz * w1z;
        g_negPj[i * HID + m] = -p1;
        g_Pib[i * HID + m]   = p1 + b1m;

        if (m < H) {
            float s = 0.f;
#pragma unroll
            for (int d = 0; d < HD; d++) s += qrow[m * HD + d] * b2s[m * HD + d];
            g_qb2[i * H + m] = s;
        }
    }
}

// ---------------------------------------------------------------
// K3: scores -> es = exp(score) + row-sum partials (unchanged R14).
// ---------------------------------------------------------------
struct ScoresSmem {
    float  qs[TI][132];
    float  ksT[C][TJ + 4];
    float  Pib[TI][HID];
    float  nPjT[HID][TJ + 4];
    float4 A4[TI][HID + 2];
    float  pis[TI][3];
    float  pjs[TJ][3];
    float  qb2[TI][4];
};

__global__ void __launch_bounds__(256, 2) scores_kernel(const float* __restrict__ pos) {
    extern __shared__ __align__(16) char s_raw[];
    ScoresSmem& s = *reinterpret_cast<ScoresSmem*>(s_raw);

    int jb = blockIdx.x;
    int i0 = blockIdx.y * TI;
    int j0 = jb * TJ;
    int tid = threadIdx.x;
    const float inv_sqrt_hd = 0.17677669529663687f;

    {
        const float4* gq4 = (const float4*)g_q;
        for (int t = tid; t < TI * 32; t += 256) {
            int r = t >> 5, c4 = t & 31;
            float4 v = gq4[(i0 + r) * 32 + c4];
            v.x *= inv_sqrt_hd; v.y *= inv_sqrt_hd; v.z *= inv_sqrt_hd; v.w *= inv_sqrt_hd;
            *(float4*)&s.qs[r][c4 * 4] = v;
        }
        const float4* gk4 = (const float4*)g_k;
        for (int t = tid; t < TJ * 32; t += 256) {
            int j = t >> 5, c4 = t & 31;
            float4 v = gk4[(j0 + j) * 32 + c4];
            s.ksT[c4 * 4 + 0][j] = v.x;
            s.ksT[c4 * 4 + 1][j] = v.y;
            s.ksT[c4 * 4 + 2][j] = v.z;
            s.ksT[c4 * 4 + 3][j] = v.w;
        }
        const float4* gp4 = (const float4*)g_negPj;
        for (int t = tid; t < TJ * 16; t += 256) {
            int j = t >> 4, m4 = t & 15;
            float4 v = gp4[(j0 + j) * 16 + m4];
            s.nPjT[m4 * 4 + 0][j] = v.x;
            s.nPjT[m4 * 4 + 1][j] = v.y;
            s.nPjT[m4 * 4 + 2][j] = v.z;
            s.nPjT[m4 * 4 + 3][j] = v.w;
        }
    }
    for (int t = tid; t < TI * HID; t += 256) {
        int r = t >> 6, m = t & 63;
        s.Pib[r][m] = g_Pib[(i0 + r) * HID + m];
        s.A4[r][m]  = g_A4[(i0 + r) * HID + m];
    }
    if (tid < TI) {
        s.pis[tid][0] = pos[(i0 + tid) * 3 + 0];
        s.pis[tid][1] = pos[(i0 + tid) * 3 + 1];
        s.pis[tid][2] = pos[(i0 + tid) * 3 + 2];
    }
    if (tid < TJ) {
        s.pjs[tid][0] = pos[(j0 + tid) * 3 + 0];
        s.pjs[tid][1] = pos[(j0 + tid) * 3 + 1];
        s.pjs[tid][2] = pos[(j0 + tid) * 3 + 2];
    }
    if (tid < TI * H) {
        s.qb2[tid >> 2][tid & 3] = g_qb2[(i0 + (tid >> 2)) * H + (tid & 3)];
    }
    __syncthreads();

    int il = tid >> 4;
    int jt = tid & 15;
    int ia = il, ib = il + 16;
    int jq = 4 * jt;

    u64 acc[2][4][2];
#pragma unroll
    for (int h = 0; h < 4; h++) {
        float qa = s.qb2[ia][h], qb = s.qb2[ib][h];
        u64 ta, tb;
        PACK2(ta, qa, qa); PACK2(tb, qb, qb);
        acc[0][h][0] = ta; acc[0][h][1] = ta;
        acc[1][h][0] = tb; acc[1][h][1] = tb;
    }

#pragma unroll 4
    for (int m = 0; m < HID; m++) {
        float pa = s.Pib[ia][m], pb = s.Pib[ib][m];
        u64 pa2, pb2;
        PACK2(pa2, pa, pa); PACK2(pb2, pb, pb);
        ulonglong2 nn = *(const ulonglong2*)&s.nPjT[m][jq];

        u64 za0, za1, zb0, zb1;
        ADD2(za0, pa2, nn.x); ADD2(za1, pa2, nn.y);
        ADD2(zb0, pb2, nn.x); ADD2(zb1, pb2, nn.y);

        float lo, hi;
        u64 ha0, ha1, hb0, hb1;
        UNPACK2(lo, hi, za0); PACK2(ha0, fmaxf(lo, 0.f), fmaxf(hi, 0.f));
        UNPACK2(lo, hi, za1); PACK2(ha1, fmaxf(lo, 0.f), fmaxf(hi, 0.f));
        UNPACK2(lo, hi, zb0); PACK2(hb0, fmaxf(lo, 0.f), fmaxf(hi, 0.f));
        UNPACK2(lo, hi, zb1); PACK2(hb1, fmaxf(lo, 0.f), fmaxf(hi, 0.f));

        float4 aa = s.A4[ia][m], ab = s.A4[ib][m];
        u64 ax, ay, az, aw, bx, by, bz, bw;
        PACK2(ax, aa.x, aa.x); PACK2(ay, aa.y, aa.y);
        PACK2(az, aa.z, aa.z); PACK2(aw, aa.w, aa.w);
        PACK2(bx, ab.x, ab.x); PACK2(by, ab.y, ab.y);
        PACK2(bz, ab.z, ab.z); PACK2(bw, ab.w, ab.w);

        FMA2(acc[0][0][0], ha0, ax); FMA2(acc[0][0][1], ha1, ax);
        FMA2(acc[0][1][0], ha0, ay); FMA2(acc[0][1][1], ha1, ay);
        FMA2(acc[0][2][0], ha0, az); FMA2(acc[0][2][1], ha1, az);
        FMA2(acc[0][3][0], ha0, aw); FMA2(acc[0][3][1], ha1, aw);
        FMA2(acc[1][0][0], hb0, bx); FMA2(acc[1][0][1], hb1, bx);
        FMA2(acc[1][1][0], hb0, by); FMA2(acc[1][1][1], hb1, by);
        FMA2(acc[1][2][0], hb0, bz); FMA2(acc[1][2][1], hb1, bz);
        FMA2(acc[1][3][0], hb0, bw); FMA2(acc[1][3][1], hb1, bw);
    }

#pragma unroll
    for (int h = 0; h < 4; h++) {
#pragma unroll
        for (int d2 = 0; d2 < 16; d2++) {
            int c = h * HD + 2 * d2;
            float2 qa = *(const float2*)&s.qs[ia][c];
            float2 qb = *(const float2*)&s.qs[ib][c];
            ulonglong2 k0 = *(const ulonglong2*)&s.ksT[c][jq];
            ulonglong2 k1 = *(const ulonglong2*)&s.ksT[c + 1][jq];
            u64 qa0, qa1, qb0, qb1;
            PACK2(qa0, qa.x, qa.x); PACK2(qa1, qa.y, qa.y);
            PACK2(qb0, qb.x, qb.x); PACK2(qb1, qb.y, qb.y);
            FMA2(acc[0][h][0], qa0, k0.x); FMA2(acc[0][h][1], qa0, k0.y);
            FMA2(acc[0][h][0], qa1, k1.x); FMA2(acc[0][h][1], qa1, k1.y);
            FMA2(acc[1][h][0], qb0, k0.x); FMA2(acc[1][h][1], qb0, k0.y);
            FMA2(acc[1][h][0], qb1, k1.x); FMA2(acc[1][h][1], qb1, k1.y);
        }
    }

    float pax = s.pis[ia][0], pay = s.pis[ia][1], paz = s.pis[ia][2];
    float pbx = s.pis[ib][0], pby = s.pis[ib][1], pbz = s.pis[ib][2];
    float da[4], db[4];
#pragma unroll
    for (int e = 0; e < 4; e++) {
        int j = jq + e;
        float jx = s.pjs[j][0], jy = s.pjs[j][1], jz = s.pjs[j][2];
        float x0 = pax - jx, y0_ = pay - jy, z0 = paz - jz;
        float x1 = pbx - jx, y1_ = pby - jy, z1 = pbz - jz;
        da[e] = sqrtf(x0 * x0 + y0_ * y0_ + z0 * z0);
        db[e] = sqrtf(x1 * x1 + y1_ * y1_ + z1 * z1);
    }

    int iga = i0 + ia, igb = i0 + ib;
    float lsum[2][4];
#pragma unroll
    for (int h = 0; h < 4; h++) {
        size_t basea = ((size_t)h * N + iga) * N + j0 + jq;
        size_t baseb = ((size_t)h * N + igb) * N + j0 + jq;
        float l0, h0, l1, h1;
        UNPACK2(l0, h0, acc[0][h][0]);
        UNPACK2(l1, h1, acc[0][h][1]);
        float4 ea = make_float4(__expf(l0 - da[0]), __expf(h0 - da[1]),
                                __expf(l1 - da[2]), __expf(h1 - da[3]));
        UNPACK2(l0, h0, acc[1][h][0]);
        UNPACK2(l1, h1, acc[1][h][1]);
        float4 eb = make_float4(__expf(l0 - db[0]), __expf(h0 - db[1]),
                                __expf(l1 - db[2]), __expf(h1 - db[3]));
        *(float4*)&g_es[basea] = ea;
        *(float4*)&g_es[baseb] = eb;
        lsum[0][h] = (ea.x + ea.y) + (ea.z + ea.w);
        lsum[1][h] = (eb.x + eb.y) + (eb.z + eb.w);
    }

#pragma unroll
    for (int o = 1; o < 16; o <<= 1) {
#pragma unroll
        for (int h = 0; h < 4; h++) {
            lsum[0][h] += __shfl_xor_sync(0xFFFFFFFFu, lsum[0][h], o);
            lsum[1][h] += __shfl_xor_sync(0xFFFFFFFFu, lsum[1][h], o);
        }
    }
    if (jt == 0) {
#pragma unroll
        for (int h = 0; h < 4; h++) {
            g_psum[(iga * H + h) * NJB + jb] = lsum[0][h];
            g_psum[(igb * H + h) * NJB + jb] = lsum[1][h];
        }
    }
}

// ---------------------------------------------------------------
// K4 v8: PV with cp.async double-buffered es staging.
// grid (N/8, H), block 256 (8 warps). 8 chunks of 128 j:
// chunk c+1 prefetched (zero-register LDGSTS) while chunk c is
// computed from smem broadcast LDS.128. Warp w owns 16 j of each
// chunk for all 8 rows.
// ---------------------------------------------------------------
struct PVSmem {
    float es_buf[2][8][132];   // chunk: 8 rows x 128 j, padded rows
    float red[8][8][33];
};

__global__ void __launch_bounds__(256) pv_kernel(float* __restrict__ out) {
    __shared__ __align__(16) PVSmem s;

    int h = blockIdx.y;
    int i0 = blockIdx.x * 8;
    int warp = threadIdx.x >> 5, lane = threadIdx.x & 31;

    const float* vb    = g_v + h * HD + lane;                 // column d = lane
    const float* ebase = g_es + ((size_t)h * N + i0) * N;     // 8 rows, stride N

    float acc[8];
#pragma unroll
    for (int r = 0; r < 8; r++) acc[r] = 0.f;

    // stage chunk 0
    {
        const float* src = ebase + (size_t)warp * N + 0 * 128 + lane * 4;
        unsigned int dst = (unsigned int)__cvta_generic_to_shared(
            &s.es_buf[0][warp][lane * 4]);
        CP_ASYNC_16(dst, src);
        CP_ASYNC_COMMIT();
    }

#pragma unroll 1
    for (int cch = 0; cch < 8; cch++) {
        int buf = cch & 1;
        if (cch < 7) {
            const float* src = ebase + (size_t)warp * N + (cch + 1) * 128 + lane * 4;
            unsigned int dst = (unsigned int)__cvta_generic_to_shared(
                &s.es_buf[buf ^ 1][warp][lane * 4]);
            CP_ASYNC_16(dst, src);
            CP_ASYNC_COMMIT();
            CP_ASYNC_WAIT1();
        } else {
            CP_ASYNC_WAIT0();
        }
        __syncthreads();

        // compute: warp owns j-sub [warp*16, warp*16+16) of this chunk
        int jl0 = warp * 16;
        int jg0 = cch * 128 + jl0;   // global j of first owned element
#pragma unroll
        for (int q4 = 0; q4 < 4; q4++) {
            int jl = jl0 + q4 * 4;
            int jg = jg0 + q4 * 4;
            float v0 = vb[(jg + 0) * C];
            float v1 = vb[(jg + 1) * C];
            float v2 = vb[(jg + 2) * C];
            float v3 = vb[(jg + 3) * C];
#pragma unroll
            for (int r = 0; r < 8; r++) {
                float4 e = *(const float4*)&s.es_buf[buf][r][jl];
                acc[r] += e.x * v0 + e.y * v1 + e.z * v2 + e.w * v3;
            }
        }
        __syncthreads();
    }

#pragma unroll
    for (int r = 0; r < 8; r++) s.red[warp][r][lane] = acc[r];
    __syncthreads();

    // 256 outputs (8 rows x 32 d), one per thread; sums from g_psum
    {
        int o = threadIdx.x;
        int r = o >> 5, d = o & 31;
        float v = 0.f;
#pragma unroll
        for (int w = 0; w < 8; w++) v += s.red[w][r][d];

        const float4* ps = (const float4*)&g_psum[((i0 + r) * H + h) * NJB];
        float4 p0 = ps[0], p1 = ps[1], p2 = ps[2], p3 = ps[3];
        float sm = ((p0.x + p0.y) + (p0.z + p0.w)) + ((p1.x + p1.y) + (p1.z + p1.w))
                 + ((p2.x + p2.y) + (p2.z + p2.w)) + ((p3.x + p3.y) + (p3.z + p3.w));
        out[(i0 + r) * C + h * HD + d] = v / sm;
    }
}

// ---------------------------------------------------------------
extern "C" void kernel_launch(void* const* d_in, const int* in_sizes, int n_in,
                              void* d_out, int out_size) {
    (void)in_sizes; (void)n_in; (void)out_size;
    const float* x   = (const float*)d_in[0];
    const float* y   = (const float*)d_in[1];
    const float* pos = (const float*)d_in[2];
    const float* Wq  = (const float*)d_in[3];
    const float* bq  = (const float*)d_in[4];
    const float* Wk  = (const float*)d_in[5];
    const float* bk  = (const float*)d_in[6];
    const float* Wv  = (const float*)d_in[7];
    const float* bv  = (const float*)d_in[8];
    const float* W1  = (const float*)d_in[9];
    const float* b1  = (const float*)d_in[10];
    const float* W2  = (const float*)d_in[11];
    const float* b2  = (const float*)d_in[12];
    float* out = (float*)d_out;

    static bool attrs_set = false;
    if (!attrs_set) {
        cudaFuncSetAttribute(scores_kernel, cudaFuncAttributeMaxDynamicSharedMemorySize,
                             (int)sizeof(ScoresSmem));
        attrs_set = true;
    }

    qkv_kernel<<<dim3(N / 8, 3), 256>>>(x, y, Wq, bq, Wk, bk, Wv, bv);
    prep_kernel<<<N / 16, 256>>>(pos, W1, b1, W2, b2);
    scores_kernel<<<dim3(NJB, N / TI), 256, sizeof(ScoresSmem)>>>(pos);
    pv_kernel<<<dim3(N / 8, H), 256>>>(out);
}